// round 13
// baseline (speedup 1.0000x reference)
#include <cuda_runtime.h>

// ---------------------------------------------------------------------------
// 2-layer LSTM (H=512) encode (T=1024) + AR decode (64 outputs), batch row 255
// only (the reference output depends only on that row).
//
// Persistent kernel, 128 CTAs x 256 threads = 1024 warps, types MIXED per CTA:
//   warps 0..3 of every CTA: type-1 (layer-1 cell), k = 4*bid + w
//   warps 4..7 of every CTA: type-2 (layer-2 cell), k = 4*bid + (w-4)
// -> every SMSP runs one type-1 + one type-2 warp: balanced FMA time.
//
// ENCODE pipelined (layer-2 lags one step): ONE barrier per encode step.
// AR decode: two barriers/step.
//
// Grid barrier v3: 128 arrival slots PACKED into 4 cache lines. Arrive =
// one st.release per CTA. Poll = each lane ld.relaxed.v4 over its 4 slots
// (one load per iteration, ~300cyc, vs 4 serialized acquire loads before),
// vote, then ONE fence.acq_rel.gpu. Monotonic epochs; init kernel resets.
// ---------------------------------------------------------------------------

#define GRID   128
#define TPB    256
#define HH     512
#define T_ENC  1024
#define PRED   64

// ---- persistent device state (reset by init kernel every launch) -----------
__device__ __align__(16) float g_h1[2][HH];
__device__ __align__(16) float g_h2[2][HH];
__device__ __align__(128) unsigned g_arrive[GRID];   // packed: 4 x 128B lines

__global__ void lstm_init_kernel() {
    int i = threadIdx.x;
    for (int j = i; j < HH; j += blockDim.x) {
        g_h1[0][j] = 0.f; g_h1[1][j] = 0.f;
        g_h2[0][j] = 0.f; g_h2[1][j] = 0.f;
    }
    if (i < GRID) g_arrive[i] = 0u;
}

// ---- sync primitives ---------------------------------------------------------
__device__ __forceinline__ void st_release(unsigned* p, unsigned v) {
    asm volatile("st.release.gpu.u32 [%0], %1;" :: "l"(p), "r"(v) : "memory");
}
__device__ __forceinline__ uint4 ld_relaxed_v4(const uint4* p) {
    uint4 v;
    asm volatile("ld.relaxed.gpu.v4.u32 {%0,%1,%2,%3}, [%4];"
                 : "=r"(v.x), "=r"(v.y), "=r"(v.z), "=r"(v.w) : "l"(p) : "memory");
    return v;
}

// Grid barrier: CTA leader releases its packed slot; warp 0 polls all 128
// slots with one v4 relaxed load per lane, then one acquire-class fence.
__device__ __forceinline__ void grid_sync(unsigned& ep, int bid) {
    __syncthreads();                       // CTA's stores done before release
    ep += 1u;
    if (threadIdx.x == 0) st_release(&g_arrive[bid], ep);
    if (threadIdx.x < 32) {
        const uint4* p = reinterpret_cast<const uint4*>(g_arrive) + threadIdx.x;
        bool ok;
        do {
            uint4 v = ld_relaxed_v4(p);
            ok = __all_sync(0xffffffffu,
                            v.x >= ep && v.y >= ep && v.z >= ep && v.w >= ep);
        } while (!ok);
        asm volatile("fence.acq_rel.gpu;" ::: "memory");  // acquire for the CTA
    }
    __syncthreads();                       // publish to all warps
}

// ---- math helpers ------------------------------------------------------------
__device__ __forceinline__ float warp_sum(float s) {
#pragma unroll
    for (int o = 16; o; o >>= 1) s += __shfl_xor_sync(0xffffffffu, s, o);
    return s;
}

__device__ __forceinline__ void load_h_cg(const float* buf, float4 h[4], int lane) {
    const float4* b4 = reinterpret_cast<const float4*>(buf);
#pragma unroll
    for (int j = 0; j < 4; j++) h[j] = __ldcg(&b4[lane + 32 * j]);
}

// 4 register-weight row-dots vs h, interleaved butterfly allreduce.
__device__ __forceinline__ void mv4(const float4 w[4][4], const float4 h[4], float s[4]) {
#pragma unroll
    for (int g = 0; g < 4; ++g) {
        float a = 0.f;
#pragma unroll
        for (int j = 0; j < 4; ++j) {
            a = fmaf(w[g][j].x, h[j].x, a);
            a = fmaf(w[g][j].y, h[j].y, a);
            a = fmaf(w[g][j].z, h[j].z, a);
            a = fmaf(w[g][j].w, h[j].w, a);
        }
        s[g] = a;
    }
#pragma unroll
    for (int o = 16; o; o >>= 1)
#pragma unroll
        for (int g = 0; g < 4; ++g) s[g] += __shfl_xor_sync(0xffffffffu, s[g], o);
}

// 8 dots (two matrices x 4 gates), interleaved butterfly allreduce.
__device__ __forceinline__ void mv8(const float4 wa[4][4], const float4 ha[4],
                                    const float4 wb[4][4], const float4 hb[4],
                                    float s[8]) {
#pragma unroll
    for (int g = 0; g < 4; ++g) {
        float a = 0.f, b = 0.f;
#pragma unroll
        for (int j = 0; j < 4; ++j) {
            a = fmaf(wa[g][j].x, ha[j].x, a);
            a = fmaf(wa[g][j].y, ha[j].y, a);
            a = fmaf(wa[g][j].z, ha[j].z, a);
            a = fmaf(wa[g][j].w, ha[j].w, a);
            b = fmaf(wb[g][j].x, hb[j].x, b);
            b = fmaf(wb[g][j].y, hb[j].y, b);
            b = fmaf(wb[g][j].z, hb[j].z, b);
            b = fmaf(wb[g][j].w, hb[j].w, b);
        }
        s[g] = a; s[4 + g] = b;
    }
#pragma unroll
    for (int o = 16; o; o >>= 1)
#pragma unroll
        for (int g = 0; g < 8; ++g) s[g] += __shfl_xor_sync(0xffffffffu, s[g], o);
}

__device__ __forceinline__ float sigf(float x) { return 1.f / (1.f + __expf(-x)); }

__device__ __forceinline__ float cellf(float pi, float pf, float pg, float po, float& c) {
    float i_ = sigf(pi), f_ = sigf(pf), g_ = tanhf(pg), o_ = sigf(po);
    c = f_ * c + i_ * g_;
    return o_ * tanhf(c);
}

// ---- main persistent kernel ----------------------------------------------------
__global__ void __launch_bounds__(TPB, 1) lstm_main_kernel(
    const float* __restrict__ input,
    const float* __restrict__ Wih1, const float* __restrict__ Whh1,
    const float* __restrict__ bih1, const float* __restrict__ bhh1,
    const float* __restrict__ Wih2, const float* __restrict__ Whh2,
    const float* __restrict__ bih2, const float* __restrict__ bhh2,
    const float* __restrict__ Wlin, const float* __restrict__ blin,
    float* __restrict__ out)
{
    const int  lane = threadIdx.x & 31;
    const int  bid  = blockIdx.x;
    const int  wid  = threadIdx.x >> 5;        // 0..7
    const bool is1  = (wid < 4);               // types mixed per CTA (SMSP balance)
    const int  k    = bid * 4 + (wid & 3);     // 0..511 for each type

    // ---- one-time: this warp's weight rows -> REGISTERS ----
    float4 wA[4][4], wB[4][4];
    {
        const float4* WA = reinterpret_cast<const float4*>(is1 ? Whh1 : Whh2);
#pragma unroll
        for (int g = 0; g < 4; ++g) {
            const float4* row = WA + (size_t)(k + 512 * g) * (HH / 4);
#pragma unroll
            for (int j = 0; j < 4; ++j) wA[g][j] = __ldg(&row[lane + 32 * j]);
        }
        if (!is1) {
            const float4* WB = reinterpret_cast<const float4*>(Wih2);
#pragma unroll
            for (int g = 0; g < 4; ++g) {
                const float4* row = WB + (size_t)(k + 512 * g) * (HH / 4);
#pragma unroll
                for (int j = 0; j < 4; ++j) wB[g][j] = __ldg(&row[lane + 32 * j]);
            }
        } else {
#pragma unroll
            for (int g = 0; g < 4; ++g)
#pragma unroll
                for (int j = 0; j < 4; ++j) wB[g][j] = make_float4(0.f, 0.f, 0.f, 0.f);
        }
    }
    float4 wlin4[4];
    {
        const float4* WL = reinterpret_cast<const float4*>(Wlin);
#pragma unroll
        for (int j = 0; j < 4; ++j) wlin4[j] = __ldg(&WL[lane + 32 * j]);
    }
    float bsum[4], wx[4];
#pragma unroll
    for (int g = 0; g < 4; ++g) {
        int r = k + 512 * g;
        if (is1) { bsum[g] = __ldg(&bih1[r]) + __ldg(&bhh1[r]); wx[g] = __ldg(&Wih1[r]); }
        else     { bsum[g] = __ldg(&bih2[r]) + __ldg(&bhh2[r]); wx[g] = 0.f; }
    }
    const float blin0 = __ldg(blin);

    float cs = 0.f;          // c1 (type-1) or c2 (type-2), lane 0 of this warp
    unsigned ep = 0u;

    // ================= ENCODE: pipelined, ONE barrier per step =================
    // interval t: type-1 computes h1[t]; type-2 computes h2[t-1].
    for (int t = 0; t < T_ENC; ++t) {
        if (is1) {
            float x = __ldg(&input[255 * T_ENC + t]);
            float4 hr[4];
            load_h_cg(g_h1[t & 1], hr, lane);              // h1[t-1]
            float s[4];
            mv4(wA, hr, s);
            if (lane == 0) {
                float h = cellf(s[0] + bsum[0] + wx[0] * x,
                                s[1] + bsum[1] + wx[1] * x,
                                s[2] + bsum[2] + wx[2] * x,
                                s[3] + bsum[3] + wx[3] * x, cs);
                __stcg(&g_h1[(t + 1) & 1][k], h);          // h1[t]
            }
        } else if (t >= 1) {
            float4 h1r[4], h2r[4];
            load_h_cg(g_h1[t & 1], h1r, lane);             // h1[t-1]
            load_h_cg(g_h2[(t - 1) & 1], h2r, lane);       // h2[t-2]
            float s[8];
            mv8(wA, h2r, wB, h1r, s);                      // Whh2 dots, Wih2 dots
            if (lane == 0) {
                float h = cellf(s[0] + s[4] + bsum[0],
                                s[1] + s[5] + bsum[1],
                                s[2] + s[6] + bsum[2],
                                s[3] + s[7] + bsum[3], cs);
                __stcg(&g_h2[t & 1][k], h);                // h2[t-1]
            }
        }
        grid_sync(ep, bid);
    }

    // ================= DRAIN: compute h2[1023] =================
    if (!is1) {
        float4 h1r[4], h2r[4];
        load_h_cg(g_h1[T_ENC & 1], h1r, lane);             // h1[1023]
        load_h_cg(g_h2[(T_ENC - 1) & 1], h2r, lane);       // h2[1022]
        float s[8];
        mv8(wA, h2r, wB, h1r, s);
        if (lane == 0) {
            float h = cellf(s[0] + s[4] + bsum[0],
                            s[1] + s[5] + bsum[1],
                            s[2] + s[6] + bsum[2],
                            s[3] + s[7] + bsum[3], cs);
            __stcg(&g_h2[T_ENC & 1][k], h);                // h2[1023]
        }
    }
    grid_sync(ep, bid);

    // ================= AR DECODE: t = 1024 .. 1086, two barriers/step ==========
    for (int t = T_ENC; t < T_ENC + PRED - 1; ++t) {
        float sA[4];
        if (is1) {
            // y(t-1) = Wlin . h2[t-1] + blin   (h2[t-1] in g_h2[t&1])
            float4 h2r[4];
            load_h_cg(g_h2[t & 1], h2r, lane);
            float y = 0.f;
#pragma unroll
            for (int j = 0; j < 4; ++j) {
                y = fmaf(wlin4[j].x, h2r[j].x, y);
                y = fmaf(wlin4[j].y, h2r[j].y, y);
                y = fmaf(wlin4[j].z, h2r[j].z, y);
                y = fmaf(wlin4[j].w, h2r[j].w, y);
            }
            y = warp_sum(y) + blin0;
            if (k == 0 && lane == 0) out[t - T_ENC] = y;   // out[0..62]
            float x = y;   // bitwise identical in all type-1 warps
            float4 hr[4];
            load_h_cg(g_h1[t & 1], hr, lane);              // h1[t-1]
            float s[4];
            mv4(wA, hr, s);
            if (lane == 0) {
                float h = cellf(s[0] + bsum[0] + wx[0] * x,
                                s[1] + bsum[1] + wx[1] * x,
                                s[2] + bsum[2] + wx[2] * x,
                                s[3] + bsum[3] + wx[3] * x, cs);
                __stcg(&g_h1[(t + 1) & 1][k], h);          // h1[t]
            }
        } else {
            float4 h2r[4];
            load_h_cg(g_h2[t & 1], h2r, lane);             // h2[t-1]
            mv4(wA, h2r, sA);                              // Whh2 partials stay in regs
        }
        grid_sync(ep, bid);

        if (!is1) {
            float4 h1r[4];
            load_h_cg(g_h1[(t + 1) & 1], h1r, lane);       // h1[t]
            float s[4];
            mv4(wB, h1r, s);
            if (lane == 0) {
                float h = cellf(sA[0] + s[0] + bsum[0],
                                sA[1] + s[1] + bsum[1],
                                sA[2] + s[2] + bsum[2],
                                sA[3] + s[3] + bsum[3], cs);
                __stcg(&g_h2[(t + 1) & 1][k], h);          // h2[t]
            }
        }
        grid_sync(ep, bid);
    }

    // ================= EPILOGUE: out[63] = Wlin . h2[1086] + blin ==============
    if (bid == 0 && wid == 0) {
        float4 h2r[4];
        load_h_cg(g_h2[(T_ENC + PRED - 1) & 1], h2r, lane); // h2[1086]
        float y = 0.f;
#pragma unroll
        for (int j = 0; j < 4; ++j) {
            y = fmaf(wlin4[j].x, h2r[j].x, y);
            y = fmaf(wlin4[j].y, h2r[j].y, y);
            y = fmaf(wlin4[j].z, h2r[j].z, y);
            y = fmaf(wlin4[j].w, h2r[j].w, y);
        }
        y = warp_sum(y) + blin0;
        if (lane == 0) out[PRED - 1] = y;
    }
}

// ---------------------------------------------------------------------------
// inputs (metadata order): 0 input(256x1024 f32), 1 pred_len(i32, =64),
// 2 Wih1(2048x1), 3 Whh1(2048x512), 4 bih1(2048), 5 bhh1(2048),
// 6 Wih2(2048x512), 7 Whh2(2048x512), 8 bih2(2048), 9 bhh2(2048),
// 10 Wlin(1x512), 11 blin(1).  output: 64 f32.
// ---------------------------------------------------------------------------
extern "C" void kernel_launch(void* const* d_in, const int* in_sizes, int n_in,
                              void* d_out, int out_size) {
    (void)in_sizes; (void)n_in; (void)out_size;
    const float* input = (const float*)d_in[0];
    const float* Wih1  = (const float*)d_in[2];
    const float* Whh1  = (const float*)d_in[3];
    const float* bih1  = (const float*)d_in[4];
    const float* bhh1  = (const float*)d_in[5];
    const float* Wih2  = (const float*)d_in[6];
    const float* Whh2  = (const float*)d_in[7];
    const float* bih2  = (const float*)d_in[8];
    const float* bhh2  = (const float*)d_in[9];
    const float* Wlin  = (const float*)d_in[10];
    const float* blin  = (const float*)d_in[11];

    lstm_init_kernel<<<1, 256>>>();
    lstm_main_kernel<<<GRID, TPB>>>(input, Wih1, Whh1, bih1, bhh1,
                                    Wih2, Whh2, bih2, bhh2,
                                    Wlin, blin, (float*)d_out);
}

// round 14
// speedup vs baseline: 2.7165x; 2.7165x over previous
#include <cuda_runtime.h>

// ---------------------------------------------------------------------------
// 2-layer LSTM (H=512) encode (T=1024) + AR decode (64 outputs), batch row 255
// only (the reference output depends only on that row).
//
// Persistent kernel, 128 CTAs x 256 threads = 1024 warps, types MIXED per CTA:
//   warps 0..3: type-1 (layer-1 cell), k = 4*bid + w      (Whh1 rows in regs)
//   warps 4..7: type-2 (layer-2 cell), k = 4*bid + (w-4)  (Whh2+Wih2 in regs)
// -> every SMSP runs one type-1 + one type-2 warp: balanced FMA issue.
//
// ENCODE pipelined (layer-2 lags one step): ONE barrier per encode step.
// AR decode: two barriers/step.
//
// Grid barrier v4: 128 arrival slots, ONE PER 128B LINE (de-packed — packing
// them into 4 lines saturated those LTS slices and regressed 2.4x). Arrive =
// one st.release. Poll = each lane issues 4 INDEPENDENT ld.relaxed.gpu.u32
// (MLP=4, ~350cyc/iter vs 4 serialized acquires ~1200cyc), vote with
// __all_sync, then ONE fence.acq_rel.gpu. Monotonic epochs; init resets.
// ---------------------------------------------------------------------------

#define GRID   128
#define TPB    256
#define HH     512
#define T_ENC  1024
#define PRED   64

// ---- persistent device state (reset by init kernel every launch) -----------
__device__ __align__(16) float g_h1[2][HH];
__device__ __align__(16) float g_h2[2][HH];
__device__ __align__(128) unsigned g_arrive[GRID * 32];  // one 128B line per CTA

__global__ void lstm_init_kernel() {
    int i = threadIdx.x;
    for (int j = i; j < HH; j += blockDim.x) {
        g_h1[0][j] = 0.f; g_h1[1][j] = 0.f;
        g_h2[0][j] = 0.f; g_h2[1][j] = 0.f;
    }
    for (int j = i; j < GRID * 32; j += blockDim.x) g_arrive[j] = 0u;
}

// ---- sync primitives ---------------------------------------------------------
__device__ __forceinline__ void st_release(unsigned* p, unsigned v) {
    asm volatile("st.release.gpu.u32 [%0], %1;" :: "l"(p), "r"(v) : "memory");
}
__device__ __forceinline__ unsigned ld_relaxed(const unsigned* p) {
    unsigned v;
    asm volatile("ld.relaxed.gpu.u32 %0, [%1];" : "=r"(v) : "l"(p) : "memory");
    return v;
}

// Grid barrier: CTA leader releases its own-line slot; warp 0 polls all 128
// slots with 4 independent relaxed loads per lane, votes, then one acquire-
// class fence upgrades the observed relaxed reads to acquire semantics.
__device__ __forceinline__ void grid_sync(unsigned& ep, int bid) {
    __syncthreads();                       // CTA's stores done before release
    ep += 1u;
    if (threadIdx.x == 0) st_release(&g_arrive[bid * 32], ep);
    if (threadIdx.x < 32) {
        const int l = threadIdx.x;
        bool ok;
        do {
            unsigned v0 = ld_relaxed(&g_arrive[(l      ) * 32]);
            unsigned v1 = ld_relaxed(&g_arrive[(l +  32) * 32]);
            unsigned v2 = ld_relaxed(&g_arrive[(l +  64) * 32]);
            unsigned v3 = ld_relaxed(&g_arrive[(l +  96) * 32]);
            ok = __all_sync(0xffffffffu,
                            v0 >= ep && v1 >= ep && v2 >= ep && v3 >= ep);
        } while (!ok);
        asm volatile("fence.acq_rel.gpu;" ::: "memory");   // acquire for the CTA
    }
    __syncthreads();                       // publish to all warps
}

// ---- math helpers ------------------------------------------------------------
__device__ __forceinline__ float warp_sum(float s) {
#pragma unroll
    for (int o = 16; o; o >>= 1) s += __shfl_xor_sync(0xffffffffu, s, o);
    return s;
}

__device__ __forceinline__ void load_h_cg(const float* buf, float4 h[4], int lane) {
    const float4* b4 = reinterpret_cast<const float4*>(buf);
#pragma unroll
    for (int j = 0; j < 4; j++) h[j] = __ldcg(&b4[lane + 32 * j]);
}

// 4 register-weight row-dots vs h, interleaved butterfly allreduce.
__device__ __forceinline__ void mv4(const float4 w[4][4], const float4 h[4], float s[4]) {
#pragma unroll
    for (int g = 0; g < 4; ++g) {
        float a = 0.f;
#pragma unroll
        for (int j = 0; j < 4; ++j) {
            a = fmaf(w[g][j].x, h[j].x, a);
            a = fmaf(w[g][j].y, h[j].y, a);
            a = fmaf(w[g][j].z, h[j].z, a);
            a = fmaf(w[g][j].w, h[j].w, a);
        }
        s[g] = a;
    }
#pragma unroll
    for (int o = 16; o; o >>= 1)
#pragma unroll
        for (int g = 0; g < 4; ++g) s[g] += __shfl_xor_sync(0xffffffffu, s[g], o);
}

// 8 dots (two matrices x 4 gates), interleaved butterfly allreduce.
__device__ __forceinline__ void mv8(const float4 wa[4][4], const float4 ha[4],
                                    const float4 wb[4][4], const float4 hb[4],
                                    float s[8]) {
#pragma unroll
    for (int g = 0; g < 4; ++g) {
        float a = 0.f, b = 0.f;
#pragma unroll
        for (int j = 0; j < 4; ++j) {
            a = fmaf(wa[g][j].x, ha[j].x, a);
            a = fmaf(wa[g][j].y, ha[j].y, a);
            a = fmaf(wa[g][j].z, ha[j].z, a);
            a = fmaf(wa[g][j].w, ha[j].w, a);
            b = fmaf(wb[g][j].x, hb[j].x, b);
            b = fmaf(wb[g][j].y, hb[j].y, b);
            b = fmaf(wb[g][j].z, hb[j].z, b);
            b = fmaf(wb[g][j].w, hb[j].w, b);
        }
        s[g] = a; s[4 + g] = b;
    }
#pragma unroll
    for (int o = 16; o; o >>= 1)
#pragma unroll
        for (int g = 0; g < 8; ++g) s[g] += __shfl_xor_sync(0xffffffffu, s[g], o);
}

__device__ __forceinline__ float sigf(float x) { return 1.f / (1.f + __expf(-x)); }

__device__ __forceinline__ float cellf(float pi, float pf, float pg, float po, float& c) {
    float i_ = sigf(pi), f_ = sigf(pf), g_ = tanhf(pg), o_ = sigf(po);
    c = f_ * c + i_ * g_;
    return o_ * tanhf(c);
}

// ---- main persistent kernel ----------------------------------------------------
__global__ void __launch_bounds__(TPB, 1) lstm_main_kernel(
    const float* __restrict__ input,
    const float* __restrict__ Wih1, const float* __restrict__ Whh1,
    const float* __restrict__ bih1, const float* __restrict__ bhh1,
    const float* __restrict__ Wih2, const float* __restrict__ Whh2,
    const float* __restrict__ bih2, const float* __restrict__ bhh2,
    const float* __restrict__ Wlin, const float* __restrict__ blin,
    float* __restrict__ out)
{
    const int  lane = threadIdx.x & 31;
    const int  bid  = blockIdx.x;
    const int  wid  = threadIdx.x >> 5;        // 0..7
    const bool is1  = (wid < 4);               // types mixed per CTA (SMSP balance)
    const int  k    = bid * 4 + (wid & 3);     // 0..511 for each type

    // ---- one-time: this warp's weight rows -> REGISTERS ----
    float4 wA[4][4], wB[4][4];
    {
        const float4* WA = reinterpret_cast<const float4*>(is1 ? Whh1 : Whh2);
#pragma unroll
        for (int g = 0; g < 4; ++g) {
            const float4* row = WA + (size_t)(k + 512 * g) * (HH / 4);
#pragma unroll
            for (int j = 0; j < 4; ++j) wA[g][j] = __ldg(&row[lane + 32 * j]);
        }
        if (!is1) {
            const float4* WB = reinterpret_cast<const float4*>(Wih2);
#pragma unroll
            for (int g = 0; g < 4; ++g) {
                const float4* row = WB + (size_t)(k + 512 * g) * (HH / 4);
#pragma unroll
                for (int j = 0; j < 4; ++j) wB[g][j] = __ldg(&row[lane + 32 * j]);
            }
        } else {
#pragma unroll
            for (int g = 0; g < 4; ++g)
#pragma unroll
                for (int j = 0; j < 4; ++j) wB[g][j] = make_float4(0.f, 0.f, 0.f, 0.f);
        }
    }
    float4 wlin4[4];
    {
        const float4* WL = reinterpret_cast<const float4*>(Wlin);
#pragma unroll
        for (int j = 0; j < 4; ++j) wlin4[j] = __ldg(&WL[lane + 32 * j]);
    }
    float bsum[4], wx[4];
#pragma unroll
    for (int g = 0; g < 4; ++g) {
        int r = k + 512 * g;
        if (is1) { bsum[g] = __ldg(&bih1[r]) + __ldg(&bhh1[r]); wx[g] = __ldg(&Wih1[r]); }
        else     { bsum[g] = __ldg(&bih2[r]) + __ldg(&bhh2[r]); wx[g] = 0.f; }
    }
    const float blin0 = __ldg(blin);

    float cs = 0.f;          // c1 (type-1) or c2 (type-2), lane 0 of this warp
    unsigned ep = 0u;

    // ================= ENCODE: pipelined, ONE barrier per step =================
    // interval t: type-1 computes h1[t]; type-2 computes h2[t-1].
    for (int t = 0; t < T_ENC; ++t) {
        if (is1) {
            float x = __ldg(&input[255 * T_ENC + t]);
            float4 hr[4];
            load_h_cg(g_h1[t & 1], hr, lane);              // h1[t-1]
            float s[4];
            mv4(wA, hr, s);
            if (lane == 0) {
                float h = cellf(s[0] + bsum[0] + wx[0] * x,
                                s[1] + bsum[1] + wx[1] * x,
                                s[2] + bsum[2] + wx[2] * x,
                                s[3] + bsum[3] + wx[3] * x, cs);
                __stcg(&g_h1[(t + 1) & 1][k], h);          // h1[t]
            }
        } else if (t >= 1) {
            float4 h1r[4], h2r[4];
            load_h_cg(g_h1[t & 1], h1r, lane);             // h1[t-1]
            load_h_cg(g_h2[(t - 1) & 1], h2r, lane);       // h2[t-2]
            float s[8];
            mv8(wA, h2r, wB, h1r, s);                      // Whh2 dots, Wih2 dots
            if (lane == 0) {
                float h = cellf(s[0] + s[4] + bsum[0],
                                s[1] + s[5] + bsum[1],
                                s[2] + s[6] + bsum[2],
                                s[3] + s[7] + bsum[3], cs);
                __stcg(&g_h2[t & 1][k], h);                // h2[t-1]
            }
        }
        grid_sync(ep, bid);
    }

    // ================= DRAIN: compute h2[1023] =================
    if (!is1) {
        float4 h1r[4], h2r[4];
        load_h_cg(g_h1[T_ENC & 1], h1r, lane);             // h1[1023]
        load_h_cg(g_h2[(T_ENC - 1) & 1], h2r, lane);       // h2[1022]
        float s[8];
        mv8(wA, h2r, wB, h1r, s);
        if (lane == 0) {
            float h = cellf(s[0] + s[4] + bsum[0],
                            s[1] + s[5] + bsum[1],
                            s[2] + s[6] + bsum[2],
                            s[3] + s[7] + bsum[3], cs);
            __stcg(&g_h2[T_ENC & 1][k], h);                // h2[1023]
        }
    }
    grid_sync(ep, bid);

    // ================= AR DECODE: t = 1024 .. 1086, two barriers/step ==========
    for (int t = T_ENC; t < T_ENC + PRED - 1; ++t) {
        float sA[4];
        if (is1) {
            // y(t-1) = Wlin . h2[t-1] + blin   (h2[t-1] in g_h2[t&1])
            float4 h2r[4];
            load_h_cg(g_h2[t & 1], h2r, lane);
            float y = 0.f;
#pragma unroll
            for (int j = 0; j < 4; ++j) {
                y = fmaf(wlin4[j].x, h2r[j].x, y);
                y = fmaf(wlin4[j].y, h2r[j].y, y);
                y = fmaf(wlin4[j].z, h2r[j].z, y);
                y = fmaf(wlin4[j].w, h2r[j].w, y);
            }
            y = warp_sum(y) + blin0;
            if (k == 0 && lane == 0) out[t - T_ENC] = y;   // out[0..62]
            float x = y;   // bitwise identical in all type-1 warps
            float4 hr[4];
            load_h_cg(g_h1[t & 1], hr, lane);              // h1[t-1]
            float s[4];
            mv4(wA, hr, s);
            if (lane == 0) {
                float h = cellf(s[0] + bsum[0] + wx[0] * x,
                                s[1] + bsum[1] + wx[1] * x,
                                s[2] + bsum[2] + wx[2] * x,
                                s[3] + bsum[3] + wx[3] * x, cs);
                __stcg(&g_h1[(t + 1) & 1][k], h);          // h1[t]
            }
        } else {
            float4 h2r[4];
            load_h_cg(g_h2[t & 1], h2r, lane);             // h2[t-1]
            mv4(wA, h2r, sA);                              // Whh2 partials stay in regs
        }
        grid_sync(ep, bid);

        if (!is1) {
            float4 h1r[4];
            load_h_cg(g_h1[(t + 1) & 1], h1r, lane);       // h1[t]
            float s[4];
            mv4(wB, h1r, s);
            if (lane == 0) {
                float h = cellf(sA[0] + s[0] + bsum[0],
                                sA[1] + s[1] + bsum[1],
                                sA[2] + s[2] + bsum[2],
                                sA[3] + s[3] + bsum[3], cs);
                __stcg(&g_h2[(t + 1) & 1][k], h);          // h2[t]
            }
        }
        grid_sync(ep, bid);
    }

    // ================= EPILOGUE: out[63] = Wlin . h2[1086] + blin ==============
    if (bid == 0 && wid == 0) {
        float4 h2r[4];
        load_h_cg(g_h2[(T_ENC + PRED - 1) & 1], h2r, lane); // h2[1086]
        float y = 0.f;
#pragma unroll
        for (int j = 0; j < 4; ++j) {
            y = fmaf(wlin4[j].x, h2r[j].x, y);
            y = fmaf(wlin4[j].y, h2r[j].y, y);
            y = fmaf(wlin4[j].z, h2r[j].z, y);
            y = fmaf(wlin4[j].w, h2r[j].w, y);
        }
        y = warp_sum(y) + blin0;
        if (lane == 0) out[PRED - 1] = y;
    }
}

// ---------------------------------------------------------------------------
// inputs (metadata order): 0 input(256x1024 f32), 1 pred_len(i32, =64),
// 2 Wih1(2048x1), 3 Whh1(2048x512), 4 bih1(2048), 5 bhh1(2048),
// 6 Wih2(2048x512), 7 Whh2(2048x512), 8 bih2(2048), 9 bhh2(2048),
// 10 Wlin(1x512), 11 blin(1).  output: 64 f32.
// ---------------------------------------------------------------------------
extern "C" void kernel_launch(void* const* d_in, const int* in_sizes, int n_in,
                              void* d_out, int out_size) {
    (void)in_sizes; (void)n_in; (void)out_size;
    const float* input = (const float*)d_in[0];
    const float* Wih1  = (const float*)d_in[2];
    const float* Whh1  = (const float*)d_in[3];
    const float* bih1  = (const float*)d_in[4];
    const float* bhh1  = (const float*)d_in[5];
    const float* Wih2  = (const float*)d_in[6];
    const float* Whh2  = (const float*)d_in[7];
    const float* bih2  = (const float*)d_in[8];
    const float* bhh2  = (const float*)d_in[9];
    const float* Wlin  = (const float*)d_in[10];
    const float* blin  = (const float*)d_in[11];

    lstm_init_kernel<<<1, 256>>>();
    lstm_main_kernel<<<GRID, TPB>>>(input, Wih1, Whh1, bih1, bhh1,
                                    Wih2, Whh2, bih2, bhh2,
                                    Wlin, blin, (float*)d_out);
}